// round 13
// baseline (speedup 1.0000x reference)
#include <cuda_runtime.h>
#include <cuda_bf16.h>
#include <math.h>

#define BATCH 4096
#define NPAIR (BATCH / 2)

typedef unsigned long long u64;
typedef unsigned int u32;
typedef unsigned short u16;

// ---- packed fp32x2 helpers ----
__device__ __forceinline__ u64 pack2(float lo, float hi) {
    u64 r; asm("mov.b64 %0, {%1, %2};" : "=l"(r) : "f"(lo), "f"(hi)); return r;
}
__device__ __forceinline__ u64 fma2(u64 a, u64 b, u64 c) {
    u64 d; asm("fma.rn.f32x2 %0, %1, %2, %3;" : "=l"(d) : "l"(a), "l"(b), "l"(c));
    return d;
}
__device__ __forceinline__ void unpack2(u64 v, float& lo, float& hi) {
    asm("mov.b64 {%0, %1}, %2;" : "=f"(lo), "=f"(hi) : "l"(v));
}
__device__ __forceinline__ u64 relu2(u64 v) {
    float lo, hi; unpack2(v, lo, hi);
    return pack2(fmaxf(lo, 0.0f), fmaxf(hi, 0.0f));
}

// ---- bf16 split helpers ----
__device__ __forceinline__ float bf16r(float x) {
    return __bfloat162float(__float2bfloat16(x));
}
__device__ __forceinline__ u32 bf16pk(float lo, float hi) {
    __nv_bfloat162 t = __floats2bfloat162_rn(lo, hi);
    return reinterpret_cast<u32&>(t);
}
__device__ __forceinline__ u32 splitpk(float v) {
    const float h = bf16r(v);
    return bf16pk(h, v - h);
}

// mma.sync m16n8k16 bf16 (row.col), fp32 accumulate in-place
__device__ __forceinline__ void mma_bf16(float* d, const u32* a, const u32* b) {
    asm volatile(
        "mma.sync.aligned.m16n8k16.row.col.f32.bf16.bf16.f32 "
        "{%0,%1,%2,%3},{%4,%5,%6,%7},{%8,%9},{%0,%1,%2,%3};"
        : "+f"(d[0]), "+f"(d[1]), "+f"(d[2]), "+f"(d[3])
        : "r"(a[0]), "r"(a[1]), "r"(a[2]), "r"(a[3]), "r"(b[0]), "r"(b[1]));
}

// Intermediates
__device__ u32   g_h1b[(size_t)BATCH * 3610];        // conv1 out: split-bf16 u32
__device__ float g_h2[(size_t)BATCH * 20 * 100];     // conv2 out, planar fp32

// Pre-packed (w,w) fp32x2 weights (conv1, conv3, fc)
__device__ u64 g_w1p[1000];
__device__ u64 g_w3p[10000];
__device__ u64 g_wfp[7200];

// conv2 B fragments, lane-contiguous: [kt(63)][lane(32)][j(12)], j=nt*4+var*2+reg
__device__ u32 g_w2frag[63 * 32 * 12];

__global__ void pack_weights_kernel(
    const float* __restrict__ w1, const float* __restrict__ w3,
    const float* __restrict__ wf)
{
    const int i = blockIdx.x * 256 + threadIdx.x;
    if (i < 1000)  g_w1p[i] = pack2(w1[i], w1[i]);
    if (i < 10000) g_w3p[i] = pack2(w3[i], w3[i]);
    if (i < 7200)  g_wfp[i] = pack2(wf[i], wf[i]);
}

__global__ void pack_w2frag_kernel(const float* __restrict__ w2)
{
    int i = blockIdx.x * 256 + threadIdx.x;
    if (i >= 63 * 32 * 12) return;
    const int j = i % 12;
    const int lane = (i / 12) % 32;
    const int kt = i / (12 * 32);
    const int reg = j & 1, var = (j >> 1) & 1, nt = j >> 2;

    const int t4 = lane & 3, ocol = lane >> 2;
    const int oc = nt * 8 + ocol;
    const int k0 = kt * 16 + 2 * t4 + reg * 8;   // linear k = c*100 + ky*10 + kx
    float v0 = 0.0f, v1 = 0.0f;
    if (oc < 20) {
        if (k0 < 1000)     v0 = w2[oc * 1000 + k0];
        if (k0 + 1 < 1000) v1 = w2[oc * 1000 + k0 + 1];
    }
    const float h0 = bf16r(v0), h1 = bf16r(v1);
    const float o0 = (var == 0) ? h0 : (v0 - h0);
    const float o1 = (var == 0) ? h1 : (v1 - h1);
    g_w2frag[i] = bf16pk(o0, o1);
}

// ---------------------------------------------------------------------------
// conv1 (unchanged champion): [1,28,28] -> relu -> [10,19,19], k10.
// One block per image PAIR, 96 threads. Stores split-bf16 u32 per image.
// ---------------------------------------------------------------------------
__global__ __launch_bounds__(96, 8) void conv1_kernel(
    const float* __restrict__ x, const float* __restrict__ b1)
{
    __shared__ u64 s_in2[28 * 29];
    const int bid = blockIdx.x;
    const int tid = threadIdx.x;

    const float* x0 = x + (size_t)(2 * bid) * 784;
    const float* x1 = x0 + 784;
    for (int i = tid; i < 784; i += 96) {
        const int r = i / 28, c = i % 28;
        s_in2[r * 29 + c] = pack2(x0[i], x1[i]);
    }
    __syncthreads();

    if (tid < 95) {
        const int ocg = tid / 19, oy = tid % 19;
        const int oc0 = 2 * ocg;
        const float bv0 = __ldg(&b1[oc0]), bv1 = __ldg(&b1[oc0 + 1]);
        const u64 bi0 = pack2(bv0, bv0), bi1 = pack2(bv1, bv1);
        u32* opA = &g_h1b[(size_t)(2 * bid) * 3610 + oc0 * 361 + oy * 19];
        u32* opB = opA + 3610;

        {   // pass A: q = 0..9
            u64 a0[10], a1[10];
            #pragma unroll
            for (int q = 0; q < 10; q++) { a0[q] = bi0; a1[q] = bi1; }
            for (int ky = 0; ky < 10; ky++) {
                u64 iv[19];
                const u64* rp = &s_in2[(oy + ky) * 29];
                #pragma unroll
                for (int j = 0; j < 19; j++) iv[j] = rp[j];
                const u64* w0p = &g_w1p[oc0 * 100 + ky * 10];
                const u64* w1p = w0p + 100;
                #pragma unroll
                for (int k2 = 0; k2 < 5; k2++) {
                    const ulonglong2 wa = __ldg((const ulonglong2*)(w0p + 2 * k2));
                    const ulonglong2 wb = __ldg((const ulonglong2*)(w1p + 2 * k2));
                    #pragma unroll
                    for (int q = 0; q < 10; q++) {
                        a0[q] = fma2(iv[q + 2 * k2],     wa.x, a0[q]);
                        a0[q] = fma2(iv[q + 2 * k2 + 1], wa.y, a0[q]);
                        a1[q] = fma2(iv[q + 2 * k2],     wb.x, a1[q]);
                        a1[q] = fma2(iv[q + 2 * k2 + 1], wb.y, a1[q]);
                    }
                }
            }
            #pragma unroll
            for (int q = 0; q < 10; q++) {
                float lo, hi;
                unpack2(a0[q], lo, hi);
                opA[q] = splitpk(fmaxf(lo, 0.0f));
                opB[q] = splitpk(fmaxf(hi, 0.0f));
                unpack2(a1[q], lo, hi);
                opA[361 + q] = splitpk(fmaxf(lo, 0.0f));
                opB[361 + q] = splitpk(fmaxf(hi, 0.0f));
            }
        }
        {   // pass B: q = 10..18
            u64 a0[9], a1[9];
            #pragma unroll
            for (int q = 0; q < 9; q++) { a0[q] = bi0; a1[q] = bi1; }
            for (int ky = 0; ky < 10; ky++) {
                u64 iv[18];
                const u64* rp = &s_in2[(oy + ky) * 29 + 10];
                #pragma unroll
                for (int j = 0; j < 18; j++) iv[j] = rp[j];
                const u64* w0p = &g_w1p[oc0 * 100 + ky * 10];
                const u64* w1p = w0p + 100;
                #pragma unroll
                for (int k2 = 0; k2 < 5; k2++) {
                    const ulonglong2 wa = __ldg((const ulonglong2*)(w0p + 2 * k2));
                    const ulonglong2 wb = __ldg((const ulonglong2*)(w1p + 2 * k2));
                    #pragma unroll
                    for (int q = 0; q < 9; q++) {
                        a0[q] = fma2(iv[q + 2 * k2],     wa.x, a0[q]);
                        a0[q] = fma2(iv[q + 2 * k2 + 1], wa.y, a0[q]);
                        a1[q] = fma2(iv[q + 2 * k2],     wb.x, a1[q]);
                        a1[q] = fma2(iv[q + 2 * k2 + 1], wb.y, a1[q]);
                    }
                }
            }
            #pragma unroll
            for (int q = 0; q < 9; q++) {
                float lo, hi;
                unpack2(a0[q], lo, hi);
                opA[10 + q] = splitpk(fmaxf(lo, 0.0f));
                opB[10 + q] = splitpk(fmaxf(hi, 0.0f));
                unpack2(a1[q], lo, hi);
                opA[371 + q] = splitpk(fmaxf(lo, 0.0f));
                opB[371 + q] = splitpk(fmaxf(hi, 0.0f));
            }
        }
    }
}

// ---------------------------------------------------------------------------
// conv2 tensor-core implicit GEMM, ONE image per block (grid 4096), 128 thr.
// smem: 2 parity planes of u64 entries (hi_pair u32, lo_pair u32) -> one
// aligned LDS.64 yields both ahi and alo fragment regs (A loads 16->8).
// B fragments lane-contiguous -> 3 LDG.128 per epoch (was 12 LDG.32).
// ---------------------------------------------------------------------------
__global__ __launch_bounds__(128) void conv2_mma_kernel(const float* __restrict__ b2)
{
    __shared__ u64 s_pl2[2 * 1900];  // [parity][rr*10 + j]: lo32=hi-pair, hi32=lo-pair
    __shared__ u32 s_koff[63 * 8];   // [kt][t4][p] -> entry offset
    const int img = blockIdx.x;
    const int tid = threadIdx.x;
    const int wid = tid >> 5, lane = tid & 31;
    const int t4 = lane & 3, gr = lane >> 2;

    // --- loader: split packed u32 h1 into parity-interleaved u64 planes
    {
        u16* p0 = (u16*)&s_pl2[0];      // parity 0: u16 idx = e*4 + (ix&1) [hi], +2 [lo]
        u16* p1 = (u16*)&s_pl2[1900];   // parity 1: element ix at shifted pos ix-1
        const u32* h1p = &g_h1b[(size_t)img * 3610];
        for (int rr = tid; rr < 190; rr += 128) {       // rr = c*19 + iy
            const u32* src = h1p + rr * 19;
            const int dst = rr * 40;                     // 10 u64 = 40 u16 per row
            #pragma unroll
            for (int ix = 0; ix < 19; ix++) {
                const u32 v = src[ix];
                const u16 hi = (u16)(v & 0xffffu);
                const u16 lo = (u16)(v >> 16);
                {   // parity 0: entry ix>>1, slot ix&1
                    const int e4 = dst + (ix >> 1) * 4 + (ix & 1);
                    p0[e4]     = hi;
                    p0[e4 + 2] = lo;
                }
                if (ix > 0) {   // parity 1: element ix at position ix-1
                    const int e4 = dst + ((ix - 1) >> 1) * 4 + ((ix - 1) & 1);
                    p1[e4]     = hi;
                    p1[e4 + 2] = lo;
                }
            }
        }
    }
    // --- koff table (u64-entry offsets)
    for (int i = tid; i < 504; i += 128) {
        const int kt = i >> 3, t4i = (i >> 1) & 3, p = i & 1;
        const int k0 = kt * 16 + 2 * t4i + 8 * p;
        s_koff[i] = (k0 < 1000)
            ? (u32)((k0 / 100) * 190 + ((k0 % 100) / 10) * 10 + ((k0 % 10) >> 1))
            : 0u;
    }

    float acc[2][3][4];
    #pragma unroll
    for (int mi = 0; mi < 2; mi++)
        #pragma unroll
        for (int nt = 0; nt < 3; nt++)
            #pragma unroll
            for (int r = 0; r < 4; r++) acc[mi][nt][r] = 0.0f;

    u32 abase[2][2];
    #pragma unroll
    for (int mi = 0; mi < 2; mi++) {
        const int m = wid + 4 * mi;
        #pragma unroll
        for (int h = 0; h < 2; h++) {
            const int r = m * 16 + gr + 8 * h;
            const bool v = (m < 7) && (r < 100);
            const int oy = r / 10, ox = r % 10;
            abase[mi][h] = v ? (u32)((ox & 1) * 1900 + oy * 10 + (ox >> 1)) : 0u;
        }
    }
    __syncthreads();

    // B double buffer: 3 uint4 per epoch
    uint4 bc[3];
    {
        const uint4* bp = (const uint4*)&g_w2frag[lane * 12];
        #pragma unroll
        for (int q = 0; q < 3; q++) bc[q] = __ldg(bp + q);
    }

    #pragma unroll 1
    for (int kt = 0; kt < 63; kt++) {
        uint4 bn[3];
        const int ktn = (kt < 62) ? (kt + 1) : 62;
        {
            const uint4* bp = (const uint4*)&g_w2frag[(ktn * 32 + lane) * 12];
            #pragma unroll
            for (int q = 0; q < 3; q++) bn[q] = __ldg(bp + q);
        }
        const u32 ko0 = s_koff[kt * 8 + t4 * 2];
        const u32 ko1 = s_koff[kt * 8 + t4 * 2 + 1];
        const u32 bw[12] = {bc[0].x, bc[0].y, bc[0].z, bc[0].w,
                            bc[1].x, bc[1].y, bc[1].z, bc[1].w,
                            bc[2].x, bc[2].y, bc[2].z, bc[2].w};

        #pragma unroll
        for (int mi = 0; mi < 2; mi++) {
            if (wid + 4 * mi < 7) {
                u32 ahi[4], alo[4];
                #pragma unroll
                for (int h = 0; h < 2; h++) {
                    const u64 v0 = s_pl2[abase[mi][h] + ko0];
                    const u64 v1 = s_pl2[abase[mi][h] + ko1];
                    ahi[h]     = (u32)v0;  alo[h]     = (u32)(v0 >> 32);
                    ahi[h + 2] = (u32)v1;  alo[h + 2] = (u32)(v1 >> 32);
                }
                #pragma unroll
                for (int nt = 0; nt < 3; nt++) {
                    mma_bf16(acc[mi][nt], ahi, &bw[nt * 4]);      // ahi*bh
                    mma_bf16(acc[mi][nt], alo, &bw[nt * 4]);      // alo*bh
                    mma_bf16(acc[mi][nt], ahi, &bw[nt * 4 + 2]);  // ahi*bl
                }
            }
        }
        #pragma unroll
        for (int q = 0; q < 3; q++) bc[q] = bn[q];
    }

    // store: bias + relu, planar [img][oc][pos]
    #pragma unroll
    for (int mi = 0; mi < 2; mi++) {
        const int m = wid + 4 * mi;
        if (m >= 7) continue;
        #pragma unroll
        for (int h = 0; h < 2; h++) {
            const int r = m * 16 + gr + 8 * h;
            if (r >= 100) continue;
            float* op = &g_h2[(size_t)img * 2000 + r];
            #pragma unroll
            for (int nt = 0; nt < 3; nt++) {
                const int oc0 = nt * 8 + 2 * t4;
                if (oc0 < 20) {
                    const float v0 = acc[mi][nt][2 * h] + __ldg(&b2[oc0]);
                    op[oc0 * 100] = fmaxf(v0, 0.0f);
                }
                if (oc0 + 1 < 20) {
                    const float v1 = acc[mi][nt][2 * h + 1] + __ldg(&b2[oc0 + 1]);
                    op[(oc0 + 1) * 100] = fmaxf(v1, 0.0f);
                }
            }
        }
    }
}

// ---------------------------------------------------------------------------
// conv3 + FC (unchanged champion): one block per 2 image pairs, 128 threads.
// ---------------------------------------------------------------------------
__global__ __launch_bounds__(128) void conv3_fc_kernel(
    const float* __restrict__ b3, const float* __restrict__ bf,
    float* __restrict__ out)
{
    __shared__ u64 s_in2[2][2200];
    __shared__ u64 s_h2[2][720];
    __shared__ float s_rlo[4][10], s_rhi[4][10];

    const int bid = blockIdx.x;
    const int tid = threadIdx.x;
    const int p0 = 2 * bid;

    for (int i = tid; i < 4000; i += 128) {
        const int pq = i / 2000, rem = i % 2000;
        const int c = rem / 100, j = rem % 100;
        const int pr = p0 + pq;
        const float lo = g_h2[((size_t)(2 * pr)) * 2000 + c * 100 + j];
        const float hi = g_h2[((size_t)(2 * pr + 1)) * 2000 + c * 100 + j];
        s_in2[pq][c * 110 + (j / 10) * 11 + (j % 10)] = pack2(lo, hi);
    }

    const bool act = tid < 120;
    const int pp  = tid / 60;
    const int r   = tid % 60;
    const int ocg = r / 6, oy = r % 6;
    const int oc0 = 2 * ocg;

    u64 a0[6], a1[6];
    if (act) {
        const float bv0 = __ldg(&b3[oc0]), bv1 = __ldg(&b3[oc0 + 1]);
        const u64 bi0 = pack2(bv0, bv0), bi1 = pack2(bv1, bv1);
        #pragma unroll
        for (int q = 0; q < 6; q++) { a0[q] = bi0; a1[q] = bi1; }
    }
    __syncthreads();

    if (act) {
        for (int c = 0; c < 20; c++) {
            const u64* base = &s_in2[pp][c * 110];
            #pragma unroll
            for (int ky = 0; ky < 5; ky++) {
                u64 iv[10];
                const u64* rp = &base[(oy + ky) * 11];
                #pragma unroll
                for (int j = 0; j < 10; j++) iv[j] = rp[j];
                const u64* w0p = &g_w3p[oc0 * 500 + c * 25 + ky * 5];
                const u64* w1p = w0p + 500;
                #pragma unroll
                for (int kx = 0; kx < 5; kx++) {
                    const u64 w0  = __ldg(w0p + kx);
                    const u64 w1v = __ldg(w1p + kx);
                    #pragma unroll
                    for (int q = 0; q < 6; q++) {
                        a0[q] = fma2(iv[q + kx], w0,  a0[q]);
                        a1[q] = fma2(iv[q + kx], w1v, a1[q]);
                    }
                }
            }
        }
    }

    __syncthreads();
    if (act) {
        #pragma unroll
        for (int q = 0; q < 6; q++) {
            s_h2[pp][oc0 * 36 + oy * 6 + q]       = relu2(a0[q]);
            s_h2[pp][(oc0 + 1) * 36 + oy * 6 + q] = relu2(a1[q]);
        }
    }
    __syncthreads();

    {
        const int fpp = tid >> 6;
        const int j0  = tid & 63;
        u64 acc[10];
        #pragma unroll
        for (int o = 0; o < 10; o++) acc[o] = 0ULL;
        for (int j = j0; j < 720; j += 64) {
            const u64 v2 = s_h2[fpp][j];
            #pragma unroll
            for (int o = 0; o < 10; o++)
                acc[o] = fma2(v2, __ldg(&g_wfp[o * 720 + j]), acc[o]);
        }
        const int wd = tid >> 5;
        #pragma unroll
        for (int o = 0; o < 10; o++) {
            float lo, hi; unpack2(acc[o], lo, hi);
            #pragma unroll
            for (int s = 16; s > 0; s >>= 1) {
                lo += __shfl_down_sync(0xffffffffu, lo, s);
                hi += __shfl_down_sync(0xffffffffu, hi, s);
            }
            if ((tid & 31) == 0) { s_rlo[wd][o] = lo; s_rhi[wd][o] = hi; }
        }
    }
    __syncthreads();
    if (tid < 40) {
        const int o  = tid % 10;
        const int im = tid / 10;
        const int fpp  = im >> 1;
        const int half = im & 1;
        const int w0 = 2 * fpp;
        float v;
        if (half == 0) v = s_rlo[w0][o] + s_rlo[w0 + 1][o];
        else           v = s_rhi[w0][o] + s_rhi[w0 + 1][o];
        out[(size_t)(4 * bid + im) * 10 + o] = v + __ldg(&bf[o]);
    }
}

// ---------------------------------------------------------------------------
extern "C" void kernel_launch(void* const* d_in, const int* in_sizes, int n_in,
                              void* d_out, int out_size)
{
    (void)in_sizes; (void)n_in; (void)out_size;
    const float* x  = (const float*)d_in[0];
    const float* w1 = (const float*)d_in[1];
    const float* b1 = (const float*)d_in[2];
    const float* w2 = (const float*)d_in[3];
    const float* b2 = (const float*)d_in[4];
    const float* w3 = (const float*)d_in[5];
    const float* b3 = (const float*)d_in[6];
    const float* wf = (const float*)d_in[7];
    const float* bf = (const float*)d_in[8];
    float* out = (float*)d_out;

    pack_weights_kernel<<<40, 256>>>(w1, w3, wf);
    pack_w2frag_kernel<<<95, 256>>>(w2);
    conv1_kernel<<<NPAIR, 96>>>(x, b1);
    conv2_mma_kernel<<<BATCH, 128>>>(b2);
    conv3_fc_kernel<<<NPAIR / 2, 128>>>(b3, bf, out);
}

// round 14
// speedup vs baseline: 1.1545x; 1.1545x over previous
#include <cuda_runtime.h>
#include <cuda_bf16.h>
#include <math.h>

#define BATCH 4096
#define NPAIR (BATCH / 2)

typedef unsigned long long u64;
typedef unsigned int u32;
typedef unsigned short u16;

// ---- packed fp32x2 helpers ----
__device__ __forceinline__ u64 pack2(float lo, float hi) {
    u64 r; asm("mov.b64 %0, {%1, %2};" : "=l"(r) : "f"(lo), "f"(hi)); return r;
}
__device__ __forceinline__ u64 fma2(u64 a, u64 b, u64 c) {
    u64 d; asm("fma.rn.f32x2 %0, %1, %2, %3;" : "=l"(d) : "l"(a), "l"(b), "l"(c));
    return d;
}
__device__ __forceinline__ void unpack2(u64 v, float& lo, float& hi) {
    asm("mov.b64 {%0, %1}, %2;" : "=f"(lo), "=f"(hi) : "l"(v));
}

// ---- bf16 split helpers ----
__device__ __forceinline__ float bf16r(float x) {
    return __bfloat162float(__float2bfloat16(x));
}
__device__ __forceinline__ u32 bf16pk(float lo, float hi) {
    __nv_bfloat162 t = __floats2bfloat162_rn(lo, hi);
    return reinterpret_cast<u32&>(t);
}
__device__ __forceinline__ u32 splitpk(float v) {
    const float h = bf16r(v);
    return bf16pk(h, v - h);
}

// mma.sync m16n8k16 bf16 (row.col), fp32 accumulate in-place
__device__ __forceinline__ void mma_bf16(float* d, const u32* a, const u32* b) {
    asm volatile(
        "mma.sync.aligned.m16n8k16.row.col.f32.bf16.bf16.f32 "
        "{%0,%1,%2,%3},{%4,%5,%6,%7},{%8,%9},{%0,%1,%2,%3};"
        : "+f"(d[0]), "+f"(d[1]), "+f"(d[2]), "+f"(d[3])
        : "r"(a[0]), "r"(a[1]), "r"(a[2]), "r"(a[3]), "r"(b[0]), "r"(b[1]));
}

// Intermediates (both layers as split-bf16 packed u32)
__device__ u32 g_h1b[(size_t)BATCH * 3610];   // conv1 out
__device__ u32 g_h2b[(size_t)BATCH * 2000];   // conv2 out

// Pre-packed (w,w) fp32x2 weights (conv1, fc)
__device__ u64 g_w1p[1000];
__device__ u64 g_wfp[7200];

// B fragment tables: [kt][nt(3)][var(2)][reg(2)][lane(32)]
__device__ u32 g_w2frag[63 * 384];
__device__ u32 g_w3frag[38 * 384];

__global__ void pack_weights_kernel(
    const float* __restrict__ w1, const float* __restrict__ wf)
{
    const int i = blockIdx.x * 256 + threadIdx.x;
    if (i < 1000) g_w1p[i] = pack2(w1[i], w1[i]);
    if (i < 7200) g_wfp[i] = pack2(wf[i], wf[i]);
}

__global__ void pack_w2frag_kernel(const float* __restrict__ w2)
{
    int i = blockIdx.x * 256 + threadIdx.x;
    if (i >= 63 * 384) return;
    const int lane = i & 31;  int rest = i >> 5;
    const int reg = rest & 1; rest >>= 1;
    const int var = rest & 1; rest >>= 1;
    const int nt  = rest % 3;
    const int kt  = rest / 3;

    const int t4 = lane & 3, ocol = lane >> 2;
    const int oc = nt * 8 + ocol;
    const int k0 = kt * 16 + 2 * t4 + reg * 8;   // linear k = c*100 + ky*10 + kx
    float v0 = 0.0f, v1 = 0.0f;
    if (oc < 20) {
        if (k0 < 1000)     v0 = w2[oc * 1000 + k0];
        if (k0 + 1 < 1000) v1 = w2[oc * 1000 + k0 + 1];
    }
    const float h0 = bf16r(v0), h1 = bf16r(v1);
    const float o0 = (var == 0) ? h0 : (v0 - h0);
    const float o1 = (var == 0) ? h1 : (v1 - h1);
    g_w2frag[i] = bf16pk(o0, o1);
}

// conv3 weights, padded-K mapping: kk = c*30 + ky*6 + kx (kx 0..5, kx=5 zero)
__global__ void pack_w3frag_kernel(const float* __restrict__ w3)
{
    int i = blockIdx.x * 256 + threadIdx.x;
    if (i >= 38 * 384) return;
    const int lane = i & 31;  int rest = i >> 5;
    const int reg = rest & 1; rest >>= 1;
    const int var = rest & 1; rest >>= 1;
    const int nt  = rest % 3;
    const int kt  = rest / 3;

    const int t4 = lane & 3, ocol = lane >> 2;
    const int oc = nt * 8 + ocol;
    const int k0 = kt * 16 + 2 * t4 + reg * 8;   // even
    float v0 = 0.0f, v1 = 0.0f;
    if (oc < 20 && k0 < 600) {
        const int c = k0 / 30, rem = k0 % 30;
        const int ky = rem / 6, kx = rem % 6;    // kx even: 0,2,4
        if (kx < 5)     v0 = w3[oc * 500 + c * 25 + ky * 5 + kx];
        if (kx + 1 < 5) v1 = w3[oc * 500 + c * 25 + ky * 5 + kx + 1];
    }
    const float h0 = bf16r(v0), h1 = bf16r(v1);
    const float o0 = (var == 0) ? h0 : (v0 - h0);
    const float o1 = (var == 0) ? h1 : (v1 - h1);
    g_w3frag[i] = bf16pk(o0, o1);
}

// ---------------------------------------------------------------------------
// conv1 (unchanged champion): [1,28,28] -> relu -> [10,19,19], k10.
// ---------------------------------------------------------------------------
__global__ __launch_bounds__(96, 8) void conv1_kernel(
    const float* __restrict__ x, const float* __restrict__ b1)
{
    __shared__ u64 s_in2[28 * 29];
    const int bid = blockIdx.x;
    const int tid = threadIdx.x;

    const float* x0 = x + (size_t)(2 * bid) * 784;
    const float* x1 = x0 + 784;
    for (int i = tid; i < 784; i += 96) {
        const int r = i / 28, c = i % 28;
        s_in2[r * 29 + c] = pack2(x0[i], x1[i]);
    }
    __syncthreads();

    if (tid < 95) {
        const int ocg = tid / 19, oy = tid % 19;
        const int oc0 = 2 * ocg;
        const float bv0 = __ldg(&b1[oc0]), bv1 = __ldg(&b1[oc0 + 1]);
        const u64 bi0 = pack2(bv0, bv0), bi1 = pack2(bv1, bv1);
        u32* opA = &g_h1b[(size_t)(2 * bid) * 3610 + oc0 * 361 + oy * 19];
        u32* opB = opA + 3610;

        {   // pass A: q = 0..9
            u64 a0[10], a1[10];
            #pragma unroll
            for (int q = 0; q < 10; q++) { a0[q] = bi0; a1[q] = bi1; }
            for (int ky = 0; ky < 10; ky++) {
                u64 iv[19];
                const u64* rp = &s_in2[(oy + ky) * 29];
                #pragma unroll
                for (int j = 0; j < 19; j++) iv[j] = rp[j];
                const u64* w0p = &g_w1p[oc0 * 100 + ky * 10];
                const u64* w1p = w0p + 100;
                #pragma unroll
                for (int k2 = 0; k2 < 5; k2++) {
                    const ulonglong2 wa = __ldg((const ulonglong2*)(w0p + 2 * k2));
                    const ulonglong2 wb = __ldg((const ulonglong2*)(w1p + 2 * k2));
                    #pragma unroll
                    for (int q = 0; q < 10; q++) {
                        a0[q] = fma2(iv[q + 2 * k2],     wa.x, a0[q]);
                        a0[q] = fma2(iv[q + 2 * k2 + 1], wa.y, a0[q]);
                        a1[q] = fma2(iv[q + 2 * k2],     wb.x, a1[q]);
                        a1[q] = fma2(iv[q + 2 * k2 + 1], wb.y, a1[q]);
                    }
                }
            }
            #pragma unroll
            for (int q = 0; q < 10; q++) {
                float lo, hi;
                unpack2(a0[q], lo, hi);
                opA[q] = splitpk(fmaxf(lo, 0.0f));
                opB[q] = splitpk(fmaxf(hi, 0.0f));
                unpack2(a1[q], lo, hi);
                opA[361 + q] = splitpk(fmaxf(lo, 0.0f));
                opB[361 + q] = splitpk(fmaxf(hi, 0.0f));
            }
        }
        {   // pass B: q = 10..18
            u64 a0[9], a1[9];
            #pragma unroll
            for (int q = 0; q < 9; q++) { a0[q] = bi0; a1[q] = bi1; }
            for (int ky = 0; ky < 10; ky++) {
                u64 iv[18];
                const u64* rp = &s_in2[(oy + ky) * 29 + 10];
                #pragma unroll
                for (int j = 0; j < 18; j++) iv[j] = rp[j];
                const u64* w0p = &g_w1p[oc0 * 100 + ky * 10];
                const u64* w1p = w0p + 100;
                #pragma unroll
                for (int k2 = 0; k2 < 5; k2++) {
                    const ulonglong2 wa = __ldg((const ulonglong2*)(w0p + 2 * k2));
                    const ulonglong2 wb = __ldg((const ulonglong2*)(w1p + 2 * k2));
                    #pragma unroll
                    for (int q = 0; q < 9; q++) {
                        a0[q] = fma2(iv[q + 2 * k2],     wa.x, a0[q]);
                        a0[q] = fma2(iv[q + 2 * k2 + 1], wa.y, a0[q]);
                        a1[q] = fma2(iv[q + 2 * k2],     wb.x, a1[q]);
                        a1[q] = fma2(iv[q + 2 * k2 + 1], wb.y, a1[q]);
                    }
                }
            }
            #pragma unroll
            for (int q = 0; q < 9; q++) {
                float lo, hi;
                unpack2(a0[q], lo, hi);
                opA[10 + q] = splitpk(fmaxf(lo, 0.0f));
                opB[10 + q] = splitpk(fmaxf(hi, 0.0f));
                unpack2(a1[q], lo, hi);
                opA[371 + q] = splitpk(fmaxf(lo, 0.0f));
                opB[371 + q] = splitpk(fmaxf(hi, 0.0f));
            }
        }
    }
}

// ---------------------------------------------------------------------------
// conv2 (R12 champion structure), epilogue now emits split-bf16 u32.
// One image per block (grid 4096), 128 threads, 4 u32 planes pitch 20.
// ---------------------------------------------------------------------------
__global__ __launch_bounds__(128) void conv2_mma_kernel(const float* __restrict__ b2)
{
    __shared__ u32 s_pl[4 * 1900];   // planes: 0=hi0 1=hi1 2=lo0 3=lo1
    __shared__ u32 s_koff[63 * 8];
    const int img = blockIdx.x;
    const int tid = threadIdx.x;
    const int wid = tid >> 5, lane = tid & 31;
    const int t4 = lane & 3, gr = lane >> 2;

    {
        u16* hi0 = (u16*)&s_pl[0];
        u16* hi1 = (u16*)&s_pl[1900];
        u16* lo0 = (u16*)&s_pl[3800];
        u16* lo1 = (u16*)&s_pl[5700];
        const u32* h1p = &g_h1b[(size_t)img * 3610];
        for (int rr = tid; rr < 190; rr += 128) {       // rr = c*19 + iy
            const u32* src = h1p + rr * 19;
            const int dst = rr * 20;
            #pragma unroll
            for (int ix = 0; ix < 19; ix++) {
                const u32 v = src[ix];
                const u16 hi = (u16)(v & 0xffffu);
                const u16 lo = (u16)(v >> 16);
                hi0[dst + ix] = hi;
                lo0[dst + ix] = lo;
                if (ix > 0) {
                    hi1[dst + ix - 1] = hi;
                    lo1[dst + ix - 1] = lo;
                }
            }
        }
    }
    for (int i = tid; i < 504; i += 128) {
        const int kt = i >> 3, t4i = (i >> 1) & 3, p = i & 1;
        const int k0 = kt * 16 + 2 * t4i + 8 * p;
        s_koff[i] = (k0 < 1000)
            ? (u32)((k0 / 100) * 190 + ((k0 % 100) / 10) * 10 + ((k0 % 10) >> 1))
            : 0u;
    }

    float acc[2][3][4];
    #pragma unroll
    for (int mi = 0; mi < 2; mi++)
        #pragma unroll
        for (int nt = 0; nt < 3; nt++)
            #pragma unroll
            for (int r = 0; r < 4; r++) acc[mi][nt][r] = 0.0f;

    u32 abase[2][2];
    #pragma unroll
    for (int mi = 0; mi < 2; mi++) {
        const int m = wid + 4 * mi;
        #pragma unroll
        for (int h = 0; h < 2; h++) {
            const int r = m * 16 + gr + 8 * h;
            const bool v = (m < 7) && (r < 100);
            const int oy = r / 10, ox = r % 10;
            abase[mi][h] = v ? (u32)((ox & 1) * 1900 + oy * 10 + (ox >> 1)) : 0u;
        }
    }
    __syncthreads();

    u32 bc[12];
    {
        const u32* bp = &g_w2frag[lane];
        #pragma unroll
        for (int j = 0; j < 12; j++) bc[j] = __ldg(bp + j * 32);
    }

    #pragma unroll 1
    for (int kt = 0; kt < 63; kt++) {
        u32 bn[12];
        const int ktn = (kt < 62) ? (kt + 1) : 62;
        {
            const u32* bp = &g_w2frag[ktn * 384 + lane];
            #pragma unroll
            for (int j = 0; j < 12; j++) bn[j] = __ldg(bp + j * 32);
        }
        const u32 ko0 = s_koff[kt * 8 + t4 * 2];
        const u32 ko1 = s_koff[kt * 8 + t4 * 2 + 1];

        #pragma unroll
        for (int mi = 0; mi < 2; mi++) {
            if (wid + 4 * mi < 7) {
                u32 ahi[4], alo[4];
                #pragma unroll
                for (int h = 0; h < 2; h++) {
                    const u32 i0 = abase[mi][h] + ko0;
                    const u32 i1 = abase[mi][h] + ko1;
                    ahi[h]     = s_pl[i0];  alo[h]     = s_pl[i0 + 3800];
                    ahi[h + 2] = s_pl[i1];  alo[h + 2] = s_pl[i1 + 3800];
                }
                #pragma unroll
                for (int nt = 0; nt < 3; nt++) {
                    mma_bf16(acc[mi][nt], ahi, &bc[nt * 4]);
                    mma_bf16(acc[mi][nt], alo, &bc[nt * 4]);
                    mma_bf16(acc[mi][nt], ahi, &bc[nt * 4 + 2]);
                }
            }
        }
        #pragma unroll
        for (int j = 0; j < 12; j++) bc[j] = bn[j];
    }

    // store: bias + relu + split-bf16 pack, planar [img][oc][pos]
    #pragma unroll
    for (int mi = 0; mi < 2; mi++) {
        const int m = wid + 4 * mi;
        if (m >= 7) continue;
        #pragma unroll
        for (int h = 0; h < 2; h++) {
            const int r = m * 16 + gr + 8 * h;
            if (r >= 100) continue;
            u32* op = &g_h2b[(size_t)img * 2000 + r];
            #pragma unroll
            for (int nt = 0; nt < 3; nt++) {
                const int oc0 = nt * 8 + 2 * t4;
                if (oc0 < 20) {
                    const float v0 = acc[mi][nt][2 * h] + __ldg(&b2[oc0]);
                    op[oc0 * 100] = splitpk(fmaxf(v0, 0.0f));
                }
                if (oc0 + 1 < 20) {
                    const float v1 = acc[mi][nt][2 * h + 1] + __ldg(&b2[oc0 + 1]);
                    op[(oc0 + 1) * 100] = splitpk(fmaxf(v1, 0.0f));
                }
            }
        }
    }
}

// ---------------------------------------------------------------------------
// conv3 via MMA + FC. One block per 2 images, 128 threads.
// GEMM: M=96 (2 img x 48 padded rows of 36), N=24 (3 nt), K=600
// (kk = c*30 + ky*6 + kx, kx padded to 6 -> fragment pairs share a row).
// A planes per image: hi0@0, hi1@1000, lo0@2000, lo1@3000 (u32), pitch 5/row.
// FC: fp32x2 over the image pair.
// ---------------------------------------------------------------------------
__global__ __launch_bounds__(128) void conv3_mma_fc_kernel(
    const float* __restrict__ b3, const float* __restrict__ bf,
    float* __restrict__ out)
{
    __shared__ u32 s_pl[8000];       // [img(2)][plane(4)][1000]
    __shared__ u32 s_koff[38 * 8];
    __shared__ float s_hf[2][720];
    __shared__ float s_rlo[4][10], s_rhi[4][10];

    const int bid = blockIdx.x;
    const int tid = threadIdx.x;
    const int wid = tid >> 5, lane = tid & 31;
    const int t4 = lane & 3, gr = lane >> 2;

    for (int i = tid; i < 8000; i += 128) s_pl[i] = 0;
    for (int i = tid; i < 304; i += 128) {
        const int kt = i >> 3, t4i = (i >> 1) & 3, p = i & 1;
        const int k0 = kt * 16 + 2 * t4i + 8 * p;
        u32 v = 0;
        if (k0 < 600) {
            const int c = k0 / 30, rem = k0 % 30;
            const int ky = rem / 6, kx = rem % 6;
            v = (u32)(c * 50 + ky * 5 + (kx >> 1));
        }
        s_koff[i] = v;
    }
    __syncthreads();

    // fill planes from split-bf16 conv2 output
    {
        const u32* h2p = &g_h2b[(size_t)(2 * bid) * 2000];
        for (int i = tid; i < 4000; i += 128) {
            const int img = i / 2000, rem = i % 2000;   // rem = c*100 + iy*10 + ix
            const int rowc = rem / 10, ix = rem % 10;    // rowc = c*10 + iy
            const u32 v = h2p[i];
            const u16 hi = (u16)(v & 0xffffu);
            const u16 lo = (u16)(v >> 16);
            u16* base = (u16*)&s_pl[img * 4000];
            const int e0 = (rowc * 5 + (ix >> 1)) * 2 + (ix & 1);
            base[e0]        = hi;     // hi0
            base[4000 + e0] = lo;     // lo0
            if (ix > 0) {
                const int e1 = (rowc * 5 + ((ix - 1) >> 1)) * 2 + ((ix - 1) & 1);
                base[2000 + e1] = hi; // hi1
                base[6000 + e1] = lo; // lo1
            }
        }
    }

    float acc[2][3][4];
    #pragma unroll
    for (int mi = 0; mi < 2; mi++)
        #pragma unroll
        for (int nt = 0; nt < 3; nt++)
            #pragma unroll
            for (int r = 0; r < 4; r++) acc[mi][nt][r] = 0.0f;

    u32 abase[2][2];
    #pragma unroll
    for (int mi = 0; mi < 2; mi++) {
        const int m = wid + 4 * mi;
        #pragma unroll
        for (int h = 0; h < 2; h++) {
            const int r = m * 16 + gr + 8 * h;       // 0..95
            const int img = r / 48, pos = r % 48;
            const bool v = (m < 6) && (pos < 36);
            const int oy = pos / 6, ox = pos % 6;
            abase[mi][h] = v ? (u32)(img * 4000 + (ox & 1) * 1000 + oy * 5 + (ox >> 1)) : 0u;
        }
    }
    __syncthreads();

    u32 bc[12];
    {
        const u32* bp = &g_w3frag[lane];
        #pragma unroll
        for (int j = 0; j < 12; j++) bc[j] = __ldg(bp + j * 32);
    }

    #pragma unroll 1
    for (int kt = 0; kt < 38; kt++) {
        u32 bn[12];
        const int ktn = (kt < 37) ? (kt + 1) : 37;
        {
            const u32* bp = &g_w3frag[ktn * 384 + lane];
            #pragma unroll
            for (int j = 0; j < 12; j++) bn[j] = __ldg(bp + j * 32);
        }
        const u32 ko0 = s_koff[kt * 8 + t4 * 2];
        const u32 ko1 = s_koff[kt * 8 + t4 * 2 + 1];

        #pragma unroll
        for (int mi = 0; mi < 2; mi++) {
            if (wid + 4 * mi < 6) {
                u32 ahi[4], alo[4];
                #pragma unroll
                for (int h = 0; h < 2; h++) {
                    const u32 i0 = abase[mi][h] + ko0;
                    const u32 i1 = abase[mi][h] + ko1;
                    ahi[h]     = s_pl[i0];  alo[h]     = s_pl[i0 + 2000];
                    ahi[h + 2] = s_pl[i1];  alo[h + 2] = s_pl[i1 + 2000];
                }
                #pragma unroll
                for (int nt = 0; nt < 3; nt++) {
                    mma_bf16(acc[mi][nt], ahi, &bc[nt * 4]);
                    mma_bf16(acc[mi][nt], alo, &bc[nt * 4]);
                    mma_bf16(acc[mi][nt], ahi, &bc[nt * 4 + 2]);
                }
            }
        }
        #pragma unroll
        for (int j = 0; j < 12; j++) bc[j] = bn[j];
    }

    // store conv3 relu to s_hf
    #pragma unroll
    for (int mi = 0; mi < 2; mi++) {
        const int m = wid + 4 * mi;
        if (m >= 6) continue;
        #pragma unroll
        for (int h = 0; h < 2; h++) {
            const int r = m * 16 + gr + 8 * h;
            const int img = r / 48, pos = r % 48;
            if (pos >= 36) continue;
            #pragma unroll
            for (int nt = 0; nt < 3; nt++) {
                const int oc0 = nt * 8 + 2 * t4;
                if (oc0 < 20) {
                    const float v0 = acc[mi][nt][2 * h] + __ldg(&b3[oc0]);
                    s_hf[img][oc0 * 36 + pos] = fmaxf(v0, 0.0f);
                }
                if (oc0 + 1 < 20) {
                    const float v1 = acc[mi][nt][2 * h + 1] + __ldg(&b3[oc0 + 1]);
                    s_hf[img][(oc0 + 1) * 36 + pos] = fmaxf(v1, 0.0f);
                }
            }
        }
    }
    __syncthreads();

    // FC over the image pair, fp32x2, all 128 threads
    {
        u64 a[10];
        #pragma unroll
        for (int o = 0; o < 10; o++) a[o] = 0ULL;
        for (int j = tid; j < 720; j += 128) {
            const u64 v2 = pack2(s_hf[0][j], s_hf[1][j]);
            #pragma unroll
            for (int o = 0; o < 10; o++)
                a[o] = fma2(v2, __ldg(&g_wfp[o * 720 + j]), a[o]);
        }
        const int wd = tid >> 5;
        #pragma unroll
        for (int o = 0; o < 10; o++) {
            float lo, hi; unpack2(a[o], lo, hi);
            #pragma unroll
            for (int s = 16; s > 0; s >>= 1) {
                lo += __shfl_down_sync(0xffffffffu, lo, s);
                hi += __shfl_down_sync(0xffffffffu, hi, s);
            }
            if ((tid & 31) == 0) { s_rlo[wd][o] = lo; s_rhi[wd][o] = hi; }
        }
    }
    __syncthreads();
    if (tid < 20) {
        const int o = tid % 10;
        const int im = tid / 10;
        float v;
        if (im == 0) v = s_rlo[0][o] + s_rlo[1][o] + s_rlo[2][o] + s_rlo[3][o];
        else         v = s_rhi[0][o] + s_rhi[1][o] + s_rhi[2][o] + s_rhi[3][o];
        out[(size_t)(2 * bid + im) * 10 + o] = v + __ldg(&bf[o]);
    }
}

// ---------------------------------------------------------------------------
extern "C" void kernel_launch(void* const* d_in, const int* in_sizes, int n_in,
                              void* d_out, int out_size)
{
    (void)in_sizes; (void)n_in; (void)out_size;
    const float* x  = (const float*)d_in[0];
    const float* w1 = (const float*)d_in[1];
    const float* b1 = (const float*)d_in[2];
    const float* w2 = (const float*)d_in[3];
    const float* b2 = (const float*)d_in[4];
    const float* w3 = (const float*)d_in[5];
    const float* b3 = (const float*)d_in[6];
    const float* wf = (const float*)d_in[7];
    const float* bf = (const float*)d_in[8];
    float* out = (float*)d_out;

    pack_weights_kernel<<<29, 256>>>(w1, wf);
    pack_w2frag_kernel<<<95, 256>>>(w2);
    pack_w3frag_kernel<<<57, 256>>>(w3);
    conv1_kernel<<<NPAIR, 96>>>(x, b1);
    conv2_mma_kernel<<<BATCH, 128>>>(b2);
    conv3_mma_fc_kernel<<<NPAIR, 128>>>(b3, bf, out);
}

// round 16
// speedup vs baseline: 1.3096x; 1.1343x over previous
#include <cuda_runtime.h>
#include <cuda_bf16.h>
#include <math.h>

#define BATCH 4096
#define NPAIR (BATCH / 2)

typedef unsigned long long u64;
typedef unsigned int u32;
typedef unsigned short u16;

// ---- packed fp32x2 helpers ----
__device__ __forceinline__ u64 pack2(float lo, float hi) {
    u64 r; asm("mov.b64 %0, {%1, %2};" : "=l"(r) : "f"(lo), "f"(hi)); return r;
}
__device__ __forceinline__ u64 fma2(u64 a, u64 b, u64 c) {
    u64 d; asm("fma.rn.f32x2 %0, %1, %2, %3;" : "=l"(d) : "l"(a), "l"(b), "l"(c));
    return d;
}
__device__ __forceinline__ void unpack2(u64 v, float& lo, float& hi) {
    asm("mov.b64 {%0, %1}, %2;" : "=f"(lo), "=f"(hi) : "l"(v));
}

// ---- bf16 split helpers ----
__device__ __forceinline__ float bf16r(float x) {
    return __bfloat162float(__float2bfloat16(x));
}
__device__ __forceinline__ u32 bf16pk(float lo, float hi) {
    __nv_bfloat162 t = __floats2bfloat162_rn(lo, hi);
    return reinterpret_cast<u32&>(t);
}
__device__ __forceinline__ u32 splitpk(float v) {
    const float h = bf16r(v);
    return bf16pk(h, v - h);
}

// mma.sync m16n8k16 bf16 (row.col), fp32 accumulate in-place
__device__ __forceinline__ void mma_bf16(float* d, const u32* a, const u32* b) {
    asm volatile(
        "mma.sync.aligned.m16n8k16.row.col.f32.bf16.bf16.f32 "
        "{%0,%1,%2,%3},{%4,%5,%6,%7},{%8,%9},{%0,%1,%2,%3};"
        : "+f"(d[0]), "+f"(d[1]), "+f"(d[2]), "+f"(d[3])
        : "r"(a[0]), "r"(a[1]), "r"(a[2]), "r"(a[3]), "r"(b[0]), "r"(b[1]));
}

// Intermediates (split-bf16 packed u32)
__device__ u32 g_h1b[(size_t)BATCH * 3610];   // conv1 out
__device__ u32 g_h2b[(size_t)BATCH * 2000];   // conv2 out

// FC weights, fp32x2 (w,w)
__device__ u64 g_wfp[7200];

// B fragment tables
__device__ u32 g_w1frag[7 * 256];    // [kt][nt(2)][var(2)][reg(2)][lane(32)]
__device__ u32 g_w2frag[63 * 384];   // [kt][nt(3)][var(2)][reg(2)][lane(32)]
__device__ u32 g_w3frag[38 * 384];

__global__ void pack_wf_kernel(const float* __restrict__ wf)
{
    const int i = blockIdx.x * 256 + threadIdx.x;
    if (i < 7200) g_wfp[i] = pack2(wf[i], wf[i]);
}

__global__ void pack_w1frag_kernel(const float* __restrict__ w1)
{
    int i = blockIdx.x * 256 + threadIdx.x;
    if (i >= 7 * 256) return;
    const int lane = i & 31;  int rest = i >> 5;
    const int reg = rest & 1; rest >>= 1;
    const int var = rest & 1; rest >>= 1;
    const int nt  = rest & 1;
    const int kt  = rest >> 1;

    const int t4 = lane & 3, ocol = lane >> 2;
    const int oc = nt * 8 + ocol;
    const int k0 = kt * 16 + 2 * t4 + reg * 8;   // k = ky*10 + kx
    float v0 = 0.0f, v1 = 0.0f;
    if (oc < 10) {
        if (k0 < 100)     v0 = w1[oc * 100 + k0];
        if (k0 + 1 < 100) v1 = w1[oc * 100 + k0 + 1];
    }
    const float h0 = bf16r(v0), h1 = bf16r(v1);
    const float o0 = (var == 0) ? h0 : (v0 - h0);
    const float o1 = (var == 0) ? h1 : (v1 - h1);
    g_w1frag[i] = bf16pk(o0, o1);
}

__global__ void pack_w2frag_kernel(const float* __restrict__ w2)
{
    int i = blockIdx.x * 256 + threadIdx.x;
    if (i >= 63 * 384) return;
    const int lane = i & 31;  int rest = i >> 5;
    const int reg = rest & 1; rest >>= 1;
    const int var = rest & 1; rest >>= 1;
    const int nt  = rest % 3;
    const int kt  = rest / 3;

    const int t4 = lane & 3, ocol = lane >> 2;
    const int oc = nt * 8 + ocol;
    const int k0 = kt * 16 + 2 * t4 + reg * 8;
    float v0 = 0.0f, v1 = 0.0f;
    if (oc < 20) {
        if (k0 < 1000)     v0 = w2[oc * 1000 + k0];
        if (k0 + 1 < 1000) v1 = w2[oc * 1000 + k0 + 1];
    }
    const float h0 = bf16r(v0), h1 = bf16r(v1);
    const float o0 = (var == 0) ? h0 : (v0 - h0);
    const float o1 = (var == 0) ? h1 : (v1 - h1);
    g_w2frag[i] = bf16pk(o0, o1);
}

__global__ void pack_w3frag_kernel(const float* __restrict__ w3)
{
    int i = blockIdx.x * 256 + threadIdx.x;
    if (i >= 38 * 384) return;
    const int lane = i & 31;  int rest = i >> 5;
    const int reg = rest & 1; rest >>= 1;
    const int var = rest & 1; rest >>= 1;
    const int nt  = rest % 3;
    const int kt  = rest / 3;

    const int t4 = lane & 3, ocol = lane >> 2;
    const int oc = nt * 8 + ocol;
    const int k0 = kt * 16 + 2 * t4 + reg * 8;   // kk = c*30 + ky*6 + kx (kx pad 6)
    float v0 = 0.0f, v1 = 0.0f;
    if (oc < 20 && k0 < 600) {
        const int c = k0 / 30, rem = k0 % 30;
        const int ky = rem / 6, kx = rem % 6;
        if (kx < 5)     v0 = w3[oc * 500 + c * 25 + ky * 5 + kx];
        if (kx + 1 < 5) v1 = w3[oc * 500 + c * 25 + ky * 5 + kx + 1];
    }
    const float h0 = bf16r(v0), h1 = bf16r(v1);
    const float o0 = (var == 0) ? h0 : (v0 - h0);
    const float o1 = (var == 0) ? h1 : (v1 - h1);
    g_w3frag[i] = bf16pk(o0, o1);
}

// ---------------------------------------------------------------------------
// conv1 via MMA: [1,28,28] -> relu -> [10,19,19], k10. One image per block.
// GEMM: M=368 (361 pos padded, 23 mtiles), N=16 (10 oc, 2 nt), K=112 (7 kt).
// Input split-bf16 parity planes (u32 offsets): hi0@0, hi1@392, lo0@784,
// lo1@1176; 28 rows x 14 u32/row per plane.
// ---------------------------------------------------------------------------
__global__ __launch_bounds__(128) void conv1_mma_kernel(
    const float* __restrict__ x, const float* __restrict__ b1)
{
    __shared__ u32 s_pl[1568];
    __shared__ u32 s_koff[7 * 8];
    const int img = blockIdx.x;
    const int tid = threadIdx.x;
    const int wid = tid >> 5, lane = tid & 31;
    const int t4 = lane & 3, gr = lane >> 2;

    for (int i = tid; i < 1568; i += 128) s_pl[i] = 0;
    for (int i = tid; i < 56; i += 128) {
        const int kt = i >> 3, t4i = (i >> 1) & 3, p = i & 1;
        const int k0 = kt * 16 + 2 * t4i + 8 * p;
        s_koff[i] = (k0 < 100) ? (u32)((k0 / 10) * 14 + ((k0 % 10) >> 1)) : 0u;
    }
    __syncthreads();   // zeros land before u16 fills (avoid u32/u16 race)

    // fill planes from fp32 input (split to hi/lo bf16)
    // u16 plane offsets = 2x u32 offsets: hi0@0, hi1@784, lo0@1568, lo1@2352
    {
        u16* base = (u16*)s_pl;
        const float* xp = x + (size_t)img * 784;
        for (int i = tid; i < 784; i += 128) {
            const u32 s = splitpk(xp[i]);
            const u16 hi = (u16)(s & 0xffffu);
            const u16 lo = (u16)(s >> 16);
            const int row = i / 28, col = i % 28;
            const int e0 = (row * 14 + (col >> 1)) * 2 + (col & 1);
            base[e0]        = hi;     // hi0
            base[1568 + e0] = lo;     // lo0
            if (col > 0) {
                const int e1 = (row * 14 + ((col - 1) >> 1)) * 2 + ((col - 1) & 1);
                base[784 + e1]  = hi; // hi1
                base[2352 + e1] = lo; // lo1
            }
        }
    }

    float acc[6][2][4];
    #pragma unroll
    for (int mi = 0; mi < 6; mi++)
        #pragma unroll
        for (int nt = 0; nt < 2; nt++)
            #pragma unroll
            for (int r = 0; r < 4; r++) acc[mi][nt][r] = 0.0f;

    u32 abase[6][2];
    #pragma unroll
    for (int mi = 0; mi < 6; mi++) {
        const int m = wid + 4 * mi;
        #pragma unroll
        for (int h = 0; h < 2; h++) {
            const int r = m * 16 + gr + 8 * h;
            const bool v = (m < 23) && (r < 361);
            const int oy = (v ? r : 0) / 19, ox = (v ? r : 0) % 19;
            abase[mi][h] = v ? (u32)((ox & 1) * 392 + oy * 14 + (ox >> 1)) : 0u;
        }
    }
    __syncthreads();

    u32 bc[8];
    {
        const u32* bp = &g_w1frag[lane];
        #pragma unroll
        for (int j = 0; j < 8; j++) bc[j] = __ldg(bp + j * 32);
    }

    #pragma unroll 1
    for (int kt = 0; kt < 7; kt++) {
        u32 bn[8];
        const int ktn = (kt < 6) ? (kt + 1) : 6;
        {
            const u32* bp = &g_w1frag[ktn * 256 + lane];
            #pragma unroll
            for (int j = 0; j < 8; j++) bn[j] = __ldg(bp + j * 32);
        }
        const u32 ko0 = s_koff[kt * 8 + t4 * 2];
        const u32 ko1 = s_koff[kt * 8 + t4 * 2 + 1];

        #pragma unroll
        for (int mi = 0; mi < 6; mi++) {
            if (wid + 4 * mi < 23) {
                u32 ahi[4], alo[4];
                #pragma unroll
                for (int h = 0; h < 2; h++) {
                    const u32 i0 = abase[mi][h] + ko0;
                    const u32 i1 = abase[mi][h] + ko1;
                    ahi[h]     = s_pl[i0];  alo[h]     = s_pl[i0 + 784];
                    ahi[h + 2] = s_pl[i1];  alo[h + 2] = s_pl[i1 + 784];
                }
                #pragma unroll
                for (int nt = 0; nt < 2; nt++) {
                    mma_bf16(acc[mi][nt], ahi, &bc[nt * 4]);
                    mma_bf16(acc[mi][nt], alo, &bc[nt * 4]);
                    mma_bf16(acc[mi][nt], ahi, &bc[nt * 4 + 2]);
                }
            }
        }
        #pragma unroll
        for (int j = 0; j < 8; j++) bc[j] = bn[j];
    }

    // epilogue: bias + relu + split-bf16 pack, planar [img][oc*361 + pos]
    u32* op = &g_h1b[(size_t)img * 3610];
    #pragma unroll
    for (int mi = 0; mi < 6; mi++) {
        const int m = wid + 4 * mi;
        if (m >= 23) continue;
        #pragma unroll
        for (int h = 0; h < 2; h++) {
            const int r = m * 16 + gr + 8 * h;
            if (r >= 361) continue;
            #pragma unroll
            for (int nt = 0; nt < 2; nt++) {
                const int oc0 = nt * 8 + 2 * t4;
                if (oc0 < 10) {
                    const float v0 = acc[mi][nt][2 * h] + __ldg(&b1[oc0]);
                    op[oc0 * 361 + r] = splitpk(fmaxf(v0, 0.0f));
                }
                if (oc0 + 1 < 10) {
                    const float v1 = acc[mi][nt][2 * h + 1] + __ldg(&b1[oc0 + 1]);
                    op[(oc0 + 1) * 361 + r] = splitpk(fmaxf(v1, 0.0f));
                }
            }
        }
    }
}

// ---------------------------------------------------------------------------
// conv2 (R12/R14 champion): one image per block, 4 u32 planes pitch 20.
// ---------------------------------------------------------------------------
__global__ __launch_bounds__(128) void conv2_mma_kernel(const float* __restrict__ b2)
{
    __shared__ u32 s_pl[4 * 1900];
    __shared__ u32 s_koff[63 * 8];
    const int img = blockIdx.x;
    const int tid = threadIdx.x;
    const int wid = tid >> 5, lane = tid & 31;
    const int t4 = lane & 3, gr = lane >> 2;

    {
        u16* hi0 = (u16*)&s_pl[0];
        u16* hi1 = (u16*)&s_pl[1900];
        u16* lo0 = (u16*)&s_pl[3800];
        u16* lo1 = (u16*)&s_pl[5700];
        const u32* h1p = &g_h1b[(size_t)img * 3610];
        for (int rr = tid; rr < 190; rr += 128) {
            const u32* src = h1p + rr * 19;
            const int dst = rr * 20;
            #pragma unroll
            for (int ix = 0; ix < 19; ix++) {
                const u32 v = src[ix];
                const u16 hi = (u16)(v & 0xffffu);
                const u16 lo = (u16)(v >> 16);
                hi0[dst + ix] = hi;
                lo0[dst + ix] = lo;
                if (ix > 0) {
                    hi1[dst + ix - 1] = hi;
                    lo1[dst + ix - 1] = lo;
                }
            }
        }
    }
    for (int i = tid; i < 504; i += 128) {
        const int kt = i >> 3, t4i = (i >> 1) & 3, p = i & 1;
        const int k0 = kt * 16 + 2 * t4i + 8 * p;
        s_koff[i] = (k0 < 1000)
            ? (u32)((k0 / 100) * 190 + ((k0 % 100) / 10) * 10 + ((k0 % 10) >> 1))
            : 0u;
    }

    float acc[2][3][4];
    #pragma unroll
    for (int mi = 0; mi < 2; mi++)
        #pragma unroll
        for (int nt = 0; nt < 3; nt++)
            #pragma unroll
            for (int r = 0; r < 4; r++) acc[mi][nt][r] = 0.0f;

    u32 abase[2][2];
    #pragma unroll
    for (int mi = 0; mi < 2; mi++) {
        const int m = wid + 4 * mi;
        #pragma unroll
        for (int h = 0; h < 2; h++) {
            const int r = m * 16 + gr + 8 * h;
            const bool v = (m < 7) && (r < 100);
            const int oy = r / 10, ox = r % 10;
            abase[mi][h] = v ? (u32)((ox & 1) * 1900 + oy * 10 + (ox >> 1)) : 0u;
        }
    }
    __syncthreads();

    u32 bc[12];
    {
        const u32* bp = &g_w2frag[lane];
        #pragma unroll
        for (int j = 0; j < 12; j++) bc[j] = __ldg(bp + j * 32);
    }

    #pragma unroll 1
    for (int kt = 0; kt < 63; kt++) {
        u32 bn[12];
        const int ktn = (kt < 62) ? (kt + 1) : 62;
        {
            const u32* bp = &g_w2frag[ktn * 384 + lane];
            #pragma unroll
            for (int j = 0; j < 12; j++) bn[j] = __ldg(bp + j * 32);
        }
        const u32 ko0 = s_koff[kt * 8 + t4 * 2];
        const u32 ko1 = s_koff[kt * 8 + t4 * 2 + 1];

        #pragma unroll
        for (int mi = 0; mi < 2; mi++) {
            if (wid + 4 * mi < 7) {
                u32 ahi[4], alo[4];
                #pragma unroll
                for (int h = 0; h < 2; h++) {
                    const u32 i0 = abase[mi][h] + ko0;
                    const u32 i1 = abase[mi][h] + ko1;
                    ahi[h]     = s_pl[i0];  alo[h]     = s_pl[i0 + 3800];
                    ahi[h + 2] = s_pl[i1];  alo[h + 2] = s_pl[i1 + 3800];
                }
                #pragma unroll
                for (int nt = 0; nt < 3; nt++) {
                    mma_bf16(acc[mi][nt], ahi, &bc[nt * 4]);
                    mma_bf16(acc[mi][nt], alo, &bc[nt * 4]);
                    mma_bf16(acc[mi][nt], ahi, &bc[nt * 4 + 2]);
                }
            }
        }
        #pragma unroll
        for (int j = 0; j < 12; j++) bc[j] = bn[j];
    }

    #pragma unroll
    for (int mi = 0; mi < 2; mi++) {
        const int m = wid + 4 * mi;
        if (m >= 7) continue;
        #pragma unroll
        for (int h = 0; h < 2; h++) {
            const int r = m * 16 + gr + 8 * h;
            if (r >= 100) continue;
            u32* op = &g_h2b[(size_t)img * 2000 + r];
            #pragma unroll
            for (int nt = 0; nt < 3; nt++) {
                const int oc0 = nt * 8 + 2 * t4;
                if (oc0 < 20) {
                    const float v0 = acc[mi][nt][2 * h] + __ldg(&b2[oc0]);
                    op[oc0 * 100] = splitpk(fmaxf(v0, 0.0f));
                }
                if (oc0 + 1 < 20) {
                    const float v1 = acc[mi][nt][2 * h + 1] + __ldg(&b2[oc0 + 1]);
                    op[(oc0 + 1) * 100] = splitpk(fmaxf(v1, 0.0f));
                }
            }
        }
    }
}

// ---------------------------------------------------------------------------
// conv3 via MMA + FC (R14): one block per 2 images, 128 threads.
// ---------------------------------------------------------------------------
__global__ __launch_bounds__(128) void conv3_mma_fc_kernel(
    const float* __restrict__ b3, const float* __restrict__ bf,
    float* __restrict__ out)
{
    __shared__ u32 s_pl[8000];
    __shared__ u32 s_koff[38 * 8];
    __shared__ float s_hf[2][720];
    __shared__ float s_rlo[4][10], s_rhi[4][10];

    const int bid = blockIdx.x;
    const int tid = threadIdx.x;
    const int wid = tid >> 5, lane = tid & 31;
    const int t4 = lane & 3, gr = lane >> 2;

    for (int i = tid; i < 8000; i += 128) s_pl[i] = 0;
    for (int i = tid; i < 304; i += 128) {
        const int kt = i >> 3, t4i = (i >> 1) & 3, p = i & 1;
        const int k0 = kt * 16 + 2 * t4i + 8 * p;
        u32 v = 0;
        if (k0 < 600) {
            const int c = k0 / 30, rem = k0 % 30;
            const int ky = rem / 6, kx = rem % 6;
            v = (u32)(c * 50 + ky * 5 + (kx >> 1));
        }
        s_koff[i] = v;
    }
    __syncthreads();

    {
        const u32* h2p = &g_h2b[(size_t)(2 * bid) * 2000];
        for (int i = tid; i < 4000; i += 128) {
            const int img = i / 2000, rem = i % 2000;
            const int rowc = rem / 10, ix = rem % 10;
            const u32 v = h2p[i];
            const u16 hi = (u16)(v & 0xffffu);
            const u16 lo = (u16)(v >> 16);
            u16* base = (u16*)&s_pl[img * 4000];
            const int e0 = (rowc * 5 + (ix >> 1)) * 2 + (ix & 1);
            base[e0]        = hi;
            base[4000 + e0] = lo;
            if (ix > 0) {
                const int e1 = (rowc * 5 + ((ix - 1) >> 1)) * 2 + ((ix - 1) & 1);
                base[2000 + e1] = hi;
                base[6000 + e1] = lo;
            }
        }
    }

    float acc[2][3][4];
    #pragma unroll
    for (int mi = 0; mi < 2; mi++)
        #pragma unroll
        for (int nt = 0; nt < 3; nt++)
            #pragma unroll
            for (int r = 0; r < 4; r++) acc[mi][nt][r] = 0.0f;

    u32 abase[2][2];
    #pragma unroll
    for (int mi = 0; mi < 2; mi++) {
        const int m = wid + 4 * mi;
        #pragma unroll
        for (int h = 0; h < 2; h++) {
            const int r = m * 16 + gr + 8 * h;
            const int img = r / 48, pos = r % 48;
            const bool v = (m < 6) && (pos < 36);
            const int oy = pos / 6, ox = pos % 6;
            abase[mi][h] = v ? (u32)(img * 4000 + (ox & 1) * 1000 + oy * 5 + (ox >> 1)) : 0u;
        }
    }
    __syncthreads();

    u32 bc[12];
    {
        const u32* bp = &g_w3frag[lane];
        #pragma unroll
        for (int j = 0; j < 12; j++) bc[j] = __ldg(bp + j * 32);
    }

    #pragma unroll 1
    for (int kt = 0; kt < 38; kt++) {
        u32 bn[12];
        const int ktn = (kt < 37) ? (kt + 1) : 37;
        {
            const u32* bp = &g_w3frag[ktn * 384 + lane];
            #pragma unroll
            for (int j = 0; j < 12; j++) bn[j] = __ldg(bp + j * 32);
        }
        const u32 ko0 = s_koff[kt * 8 + t4 * 2];
        const u32 ko1 = s_koff[kt * 8 + t4 * 2 + 1];

        #pragma unroll
        for (int mi = 0; mi < 2; mi++) {
            if (wid + 4 * mi < 6) {
                u32 ahi[4], alo[4];
                #pragma unroll
                for (int h = 0; h < 2; h++) {
                    const u32 i0 = abase[mi][h] + ko0;
                    const u32 i1 = abase[mi][h] + ko1;
                    ahi[h]     = s_pl[i0];  alo[h]     = s_pl[i0 + 2000];
                    ahi[h + 2] = s_pl[i1];  alo[h + 2] = s_pl[i1 + 2000];
                }
                #pragma unroll
                for (int nt = 0; nt < 3; nt++) {
                    mma_bf16(acc[mi][nt], ahi, &bc[nt * 4]);
                    mma_bf16(acc[mi][nt], alo, &bc[nt * 4]);
                    mma_bf16(acc[mi][nt], ahi, &bc[nt * 4 + 2]);
                }
            }
        }
        #pragma unroll
        for (int j = 0; j < 12; j++) bc[j] = bn[j];
    }

    #pragma unroll
    for (int mi = 0; mi < 2; mi++) {
        const int m = wid + 4 * mi;
        if (m >= 6) continue;
        #pragma unroll
        for (int h = 0; h < 2; h++) {
            const int r = m * 16 + gr + 8 * h;
            const int img = r / 48, pos = r % 48;
            if (pos >= 36) continue;
            #pragma unroll
            for (int nt = 0; nt < 3; nt++) {
                const int oc0 = nt * 8 + 2 * t4;
                if (oc0 < 20) {
                    const float v0 = acc[mi][nt][2 * h] + __ldg(&b3[oc0]);
                    s_hf[img][oc0 * 36 + pos] = fmaxf(v0, 0.0f);
                }
                if (oc0 + 1 < 20) {
                    const float v1 = acc[mi][nt][2 * h + 1] + __ldg(&b3[oc0 + 1]);
                    s_hf[img][(oc0 + 1) * 36 + pos] = fmaxf(v1, 0.0f);
                }
            }
        }
    }
    __syncthreads();

    {
        u64 a[10];
        #pragma unroll
        for (int o = 0; o < 10; o++) a[o] = 0ULL;
        for (int j = tid; j < 720; j += 128) {
            const u64 v2 = pack2(s_hf[0][j], s_hf[1][j]);
            #pragma unroll
            for (int o = 0; o < 10; o++)
                a[o] = fma2(v2, __ldg(&g_wfp[o * 720 + j]), a[o]);
        }
        const int wd = tid >> 5;
        #pragma unroll
        for (int o = 0; o < 10; o++) {
            float lo, hi; unpack2(a[o], lo, hi);
            #pragma unroll
            for (int s = 16; s > 0; s >>= 1) {
                lo += __shfl_down_sync(0xffffffffu, lo, s);
                hi += __shfl_down_sync(0xffffffffu, hi, s);
            }
            if ((tid & 31) == 0) { s_rlo[wd][o] = lo; s_rhi[wd][o] = hi; }
        }
    }
    __syncthreads();
    if (tid < 20) {
        const int o = tid % 10;
        const int im = tid / 10;
        float v;
        if (im == 0) v = s_rlo[0][o] + s_rlo[1][o] + s_rlo[2][o] + s_rlo[3][o];
        else         v = s_rhi[0][o] + s_rhi[1][o] + s_rhi[2][o] + s_rhi[3][o];
        out[(size_t)(2 * bid + im) * 10 + o] = v + __ldg(&bf[o]);
    }
}

// ---------------------------------------------------------------------------
extern "C" void kernel_launch(void* const* d_in, const int* in_sizes, int n_in,
                              void* d_out, int out_size)
{
    (void)in_sizes; (void)n_in; (void)out_size;
    const float* x  = (const float*)d_in[0];
    const float* w1 = (const float*)d_in[1];
    const float* b1 = (const float*)d_in[2];
    const float* w2 = (const float*)d_in[3];
    const float* b2 = (const float*)d_in[4];
    const float* w3 = (const float*)d_in[5];
    const float* b3 = (const float*)d_in[6];
    const float* wf = (const float*)d_in[7];
    const float* bf = (const float*)d_in[8];
    float* out = (float*)d_out;

    pack_wf_kernel<<<29, 256>>>(wf);
    pack_w1frag_kernel<<<7, 256>>>(w1);
    pack_w2frag_kernel<<<95, 256>>>(w2);
    pack_w3frag_kernel<<<57, 256>>>(w3);
    conv1_mma_kernel<<<BATCH, 128>>>(x, b1);
    conv2_mma_kernel<<<BATCH, 128>>>(b2);
    conv3_mma_fc_kernel<<<NPAIR, 128>>>(b3, bf, out);
}

// round 17
// speedup vs baseline: 1.3622x; 1.0402x over previous
#include <cuda_runtime.h>
#include <cuda_bf16.h>
#include <math.h>

#define BATCH 4096
#define NPAIR (BATCH / 2)

typedef unsigned long long u64;
typedef unsigned int u32;
typedef unsigned short u16;

// ---- packed fp32x2 helpers ----
__device__ __forceinline__ u64 pack2(float lo, float hi) {
    u64 r; asm("mov.b64 %0, {%1, %2};" : "=l"(r) : "f"(lo), "f"(hi)); return r;
}
__device__ __forceinline__ u64 fma2(u64 a, u64 b, u64 c) {
    u64 d; asm("fma.rn.f32x2 %0, %1, %2, %3;" : "=l"(d) : "l"(a), "l"(b), "l"(c));
    return d;
}
__device__ __forceinline__ void unpack2(u64 v, float& lo, float& hi) {
    asm("mov.b64 {%0, %1}, %2;" : "=f"(lo), "=f"(hi) : "l"(v));
}

// ---- bf16 split helpers ----
__device__ __forceinline__ float bf16r(float x) {
    return __bfloat162float(__float2bfloat16(x));
}
__device__ __forceinline__ u32 bf16pk(float lo, float hi) {
    __nv_bfloat162 t = __floats2bfloat162_rn(lo, hi);
    return reinterpret_cast<u32&>(t);
}
__device__ __forceinline__ u32 splitpk(float v) {
    const float h = bf16r(v);
    return bf16pk(h, v - h);
}

// mma.sync m16n8k16 bf16 (row.col), fp32 accumulate in-place
__device__ __forceinline__ void mma_bf16(float* d, const u32* a, const u32* b) {
    asm volatile(
        "mma.sync.aligned.m16n8k16.row.col.f32.bf16.bf16.f32 "
        "{%0,%1,%2,%3},{%4,%5,%6,%7},{%8,%9},{%0,%1,%2,%3};"
        : "+f"(d[0]), "+f"(d[1]), "+f"(d[2]), "+f"(d[3])
        : "r"(a[0]), "r"(a[1]), "r"(a[2]), "r"(a[3]), "r"(b[0]), "r"(b[1]));
}

// Intermediates (split-bf16 packed u32)
__device__ u32 g_h1b[(size_t)BATCH * 3610];   // conv1 out
__device__ u32 g_h2b[(size_t)BATCH * 2000];   // conv2 out

// FC weights, fp32x2 (w,w)
__device__ u64 g_wfp[7200];

// B fragment tables: [kt][nt][var(2)][reg(2)][lane(32)]
__device__ u32 g_w1frag[7 * 256];
__device__ u32 g_w2frag[63 * 384];
__device__ u32 g_w3frag[38 * 384];

// ---------------------------------------------------------------------------
// single merged pack kernel (one launch instead of four)
// blocks [0,95): w2frag  [95,152): w3frag  [152,159): w1frag  [159,188): wf
// ---------------------------------------------------------------------------
__global__ void pack_all_kernel(
    const float* __restrict__ w1, const float* __restrict__ w2,
    const float* __restrict__ w3, const float* __restrict__ wf)
{
    const int b = blockIdx.x;
    if (b < 95) {
        int i = b * 256 + threadIdx.x;
        if (i >= 63 * 384) return;
        const int lane = i & 31;  int rest = i >> 5;
        const int reg = rest & 1; rest >>= 1;
        const int var = rest & 1; rest >>= 1;
        const int nt  = rest % 3;
        const int kt  = rest / 3;
        const int t4 = lane & 3, ocol = lane >> 2;
        const int oc = nt * 8 + ocol;
        const int k0 = kt * 16 + 2 * t4 + reg * 8;
        float v0 = 0.0f, v1 = 0.0f;
        if (oc < 20) {
            if (k0 < 1000)     v0 = w2[oc * 1000 + k0];
            if (k0 + 1 < 1000) v1 = w2[oc * 1000 + k0 + 1];
        }
        const float h0 = bf16r(v0), h1 = bf16r(v1);
        g_w2frag[i] = bf16pk((var == 0) ? h0 : (v0 - h0),
                             (var == 0) ? h1 : (v1 - h1));
    } else if (b < 152) {
        int i = (b - 95) * 256 + threadIdx.x;
        if (i >= 38 * 384) return;
        const int lane = i & 31;  int rest = i >> 5;
        const int reg = rest & 1; rest >>= 1;
        const int var = rest & 1; rest >>= 1;
        const int nt  = rest % 3;
        const int kt  = rest / 3;
        const int t4 = lane & 3, ocol = lane >> 2;
        const int oc = nt * 8 + ocol;
        const int k0 = kt * 16 + 2 * t4 + reg * 8;   // kk = c*30 + ky*6 + kx (pad 6)
        float v0 = 0.0f, v1 = 0.0f;
        if (oc < 20 && k0 < 600) {
            const int c = k0 / 30, rem = k0 % 30;
            const int ky = rem / 6, kx = rem % 6;
            if (kx < 5)     v0 = w3[oc * 500 + c * 25 + ky * 5 + kx];
            if (kx + 1 < 5) v1 = w3[oc * 500 + c * 25 + ky * 5 + kx + 1];
        }
        const float h0 = bf16r(v0), h1 = bf16r(v1);
        g_w3frag[i] = bf16pk((var == 0) ? h0 : (v0 - h0),
                             (var == 0) ? h1 : (v1 - h1));
    } else if (b < 159) {
        int i = (b - 152) * 256 + threadIdx.x;
        if (i >= 7 * 256) return;
        const int lane = i & 31;  int rest = i >> 5;
        const int reg = rest & 1; rest >>= 1;
        const int var = rest & 1; rest >>= 1;
        const int nt  = rest & 1;
        const int kt  = rest >> 1;
        const int t4 = lane & 3, ocol = lane >> 2;
        const int oc = nt * 8 + ocol;
        const int k0 = kt * 16 + 2 * t4 + reg * 8;
        float v0 = 0.0f, v1 = 0.0f;
        if (oc < 10) {
            if (k0 < 100)     v0 = w1[oc * 100 + k0];
            if (k0 + 1 < 100) v1 = w1[oc * 100 + k0 + 1];
        }
        const float h0 = bf16r(v0), h1 = bf16r(v1);
        g_w1frag[i] = bf16pk((var == 0) ? h0 : (v0 - h0),
                             (var == 0) ? h1 : (v1 - h1));
    } else {
        int i = (b - 159) * 256 + threadIdx.x;
        if (i < 7200) g_wfp[i] = pack2(wf[i], wf[i]);
    }
}

// ---------------------------------------------------------------------------
// conv1 via MMA (R16): one image per block. M=368, N=16, K=112 (7 kt).
// Ping-pong B buffers (no copy MOVs).
// ---------------------------------------------------------------------------
__global__ __launch_bounds__(128) void conv1_mma_kernel(
    const float* __restrict__ x, const float* __restrict__ b1)
{
    __shared__ u32 s_pl[1568];
    __shared__ u32 s_koff[7 * 8];
    const int img = blockIdx.x;
    const int tid = threadIdx.x;
    const int wid = tid >> 5, lane = tid & 31;
    const int t4 = lane & 3, gr = lane >> 2;

    for (int i = tid; i < 1568; i += 128) s_pl[i] = 0;
    for (int i = tid; i < 56; i += 128) {
        const int kt = i >> 3, t4i = (i >> 1) & 3, p = i & 1;
        const int k0 = kt * 16 + 2 * t4i + 8 * p;
        s_koff[i] = (k0 < 100) ? (u32)((k0 / 10) * 14 + ((k0 % 10) >> 1)) : 0u;
    }
    __syncthreads();

    {   // u16 plane offsets: hi0@0, hi1@784, lo0@1568, lo1@2352
        u16* base = (u16*)s_pl;
        const float* xp = x + (size_t)img * 784;
        for (int i = tid; i < 784; i += 128) {
            const u32 s = splitpk(xp[i]);
            const u16 hi = (u16)(s & 0xffffu);
            const u16 lo = (u16)(s >> 16);
            const int row = i / 28, col = i % 28;
            const int e0 = (row * 14 + (col >> 1)) * 2 + (col & 1);
            base[e0]        = hi;
            base[1568 + e0] = lo;
            if (col > 0) {
                const int e1 = (row * 14 + ((col - 1) >> 1)) * 2 + ((col - 1) & 1);
                base[784 + e1]  = hi;
                base[2352 + e1] = lo;
            }
        }
    }

    float acc[6][2][4];
    #pragma unroll
    for (int mi = 0; mi < 6; mi++)
        #pragma unroll
        for (int nt = 0; nt < 2; nt++)
            #pragma unroll
            for (int r = 0; r < 4; r++) acc[mi][nt][r] = 0.0f;

    u32 abase[6][2];
    #pragma unroll
    for (int mi = 0; mi < 6; mi++) {
        const int m = wid + 4 * mi;
        #pragma unroll
        for (int h = 0; h < 2; h++) {
            const int r = m * 16 + gr + 8 * h;
            const bool v = (m < 23) && (r < 361);
            const int oy = (v ? r : 0) / 19, ox = (v ? r : 0) % 19;
            abase[mi][h] = v ? (u32)((ox & 1) * 392 + oy * 14 + (ox >> 1)) : 0u;
        }
    }
    __syncthreads();

    u32 bufA[8], bufB[8];
    {
        const u32* bp = &g_w1frag[lane];
        #pragma unroll
        for (int j = 0; j < 8; j++) bufA[j] = __ldg(bp + j * 32);
    }

    #define C1_EPOCH(KT, BUF, NBUF, NKT)                                       \
    {                                                                          \
        {                                                                      \
            const u32* bp = &g_w1frag[(NKT) * 256 + lane];                     \
            _Pragma("unroll")                                                  \
            for (int j = 0; j < 8; j++) NBUF[j] = __ldg(bp + j * 32);          \
        }                                                                      \
        const u32 ko0 = s_koff[(KT) * 8 + t4 * 2];                             \
        const u32 ko1 = s_koff[(KT) * 8 + t4 * 2 + 1];                         \
        _Pragma("unroll")                                                      \
        for (int mi = 0; mi < 6; mi++) {                                       \
            if (wid + 4 * mi < 23) {                                           \
                u32 ahi[4], alo[4];                                            \
                _Pragma("unroll")                                              \
                for (int h = 0; h < 2; h++) {                                  \
                    const u32 i0 = abase[mi][h] + ko0;                         \
                    const u32 i1 = abase[mi][h] + ko1;                         \
                    ahi[h]     = s_pl[i0];  alo[h]     = s_pl[i0 + 784];       \
                    ahi[h + 2] = s_pl[i1];  alo[h + 2] = s_pl[i1 + 784];       \
                }                                                              \
                _Pragma("unroll")                                              \
                for (int nt = 0; nt < 2; nt++) {                               \
                    mma_bf16(acc[mi][nt], ahi, &BUF[nt * 4]);                  \
                    mma_bf16(acc[mi][nt], alo, &BUF[nt * 4]);                  \
                    mma_bf16(acc[mi][nt], ahi, &BUF[nt * 4 + 2]);              \
                }                                                              \
            }                                                                  \
        }                                                                      \
    }

    #pragma unroll 1
    for (int kt = 0; kt < 6; kt += 2) {
        C1_EPOCH(kt, bufA, bufB, kt + 1);
        C1_EPOCH(kt + 1, bufB, bufA, (kt + 2 < 7) ? (kt + 2) : 6);
    }
    C1_EPOCH(6, bufA, bufB, 6);
    #undef C1_EPOCH

    u32* op = &g_h1b[(size_t)img * 3610];
    #pragma unroll
    for (int mi = 0; mi < 6; mi++) {
        const int m = wid + 4 * mi;
        if (m >= 23) continue;
        #pragma unroll
        for (int h = 0; h < 2; h++) {
            const int r = m * 16 + gr + 8 * h;
            if (r >= 361) continue;
            #pragma unroll
            for (int nt = 0; nt < 2; nt++) {
                const int oc0 = nt * 8 + 2 * t4;
                if (oc0 < 10) {
                    const float v0 = acc[mi][nt][2 * h] + __ldg(&b1[oc0]);
                    op[oc0 * 361 + r] = splitpk(fmaxf(v0, 0.0f));
                }
                if (oc0 + 1 < 10) {
                    const float v1 = acc[mi][nt][2 * h + 1] + __ldg(&b1[oc0 + 1]);
                    op[(oc0 + 1) * 361 + r] = splitpk(fmaxf(v1, 0.0f));
                }
            }
        }
    }
}

// ---------------------------------------------------------------------------
// conv2 (R12/R16 champion) with ping-pong B buffers (no copy MOVs).
// ---------------------------------------------------------------------------
__global__ __launch_bounds__(128) void conv2_mma_kernel(const float* __restrict__ b2)
{
    __shared__ u32 s_pl[4 * 1900];
    __shared__ u32 s_koff[63 * 8];
    const int img = blockIdx.x;
    const int tid = threadIdx.x;
    const int wid = tid >> 5, lane = tid & 31;
    const int t4 = lane & 3, gr = lane >> 2;

    {
        u16* hi0 = (u16*)&s_pl[0];
        u16* hi1 = (u16*)&s_pl[1900];
        u16* lo0 = (u16*)&s_pl[3800];
        u16* lo1 = (u16*)&s_pl[5700];
        const u32* h1p = &g_h1b[(size_t)img * 3610];
        for (int rr = tid; rr < 190; rr += 128) {
            const u32* src = h1p + rr * 19;
            const int dst = rr * 20;
            #pragma unroll
            for (int ix = 0; ix < 19; ix++) {
                const u32 v = src[ix];
                const u16 hi = (u16)(v & 0xffffu);
                const u16 lo = (u16)(v >> 16);
                hi0[dst + ix] = hi;
                lo0[dst + ix] = lo;
                if (ix > 0) {
                    hi1[dst + ix - 1] = hi;
                    lo1[dst + ix - 1] = lo;
                }
            }
        }
    }
    for (int i = tid; i < 504; i += 128) {
        const int kt = i >> 3, t4i = (i >> 1) & 3, p = i & 1;
        const int k0 = kt * 16 + 2 * t4i + 8 * p;
        s_koff[i] = (k0 < 1000)
            ? (u32)((k0 / 100) * 190 + ((k0 % 100) / 10) * 10 + ((k0 % 10) >> 1))
            : 0u;
    }

    float acc[2][3][4];
    #pragma unroll
    for (int mi = 0; mi < 2; mi++)
        #pragma unroll
        for (int nt = 0; nt < 3; nt++)
            #pragma unroll
            for (int r = 0; r < 4; r++) acc[mi][nt][r] = 0.0f;

    u32 abase[2][2];
    #pragma unroll
    for (int mi = 0; mi < 2; mi++) {
        const int m = wid + 4 * mi;
        #pragma unroll
        for (int h = 0; h < 2; h++) {
            const int r = m * 16 + gr + 8 * h;
            const bool v = (m < 7) && (r < 100);
            const int oy = r / 10, ox = r % 10;
            abase[mi][h] = v ? (u32)((ox & 1) * 1900 + oy * 10 + (ox >> 1)) : 0u;
        }
    }
    __syncthreads();

    u32 bufA[12], bufB[12];
    {
        const u32* bp = &g_w2frag[lane];
        #pragma unroll
        for (int j = 0; j < 12; j++) bufA[j] = __ldg(bp + j * 32);
    }

    #define C2_EPOCH(KT, BUF, NBUF, NKT)                                       \
    {                                                                          \
        {                                                                      \
            const u32* bp = &g_w2frag[(NKT) * 384 + lane];                     \
            _Pragma("unroll")                                                  \
            for (int j = 0; j < 12; j++) NBUF[j] = __ldg(bp + j * 32);         \
        }                                                                      \
        const u32 ko0 = s_koff[(KT) * 8 + t4 * 2];                             \
        const u32 ko1 = s_koff[(KT) * 8 + t4 * 2 + 1];                         \
        _Pragma("unroll")                                                      \
        for (int mi = 0; mi < 2; mi++) {                                       \
            if (wid + 4 * mi < 7) {                                            \
                u32 ahi[4], alo[4];                                            \
                _Pragma("unroll")                                              \
                for (int h = 0; h < 2; h++) {                                  \
                    const u32 i0 = abase[mi][h] + ko0;                         \
                    const u32 i1 = abase[mi][h] + ko1;                         \
                    ahi[h]     = s_pl[i0];  alo[h]     = s_pl[i0 + 3800];      \
                    ahi[h + 2] = s_pl[i1];  alo[h + 2] = s_pl[i1 + 3800];      \
                }                                                              \
                _Pragma("unroll")                                              \
                for (int nt = 0; nt < 3; nt++) {                               \
                    mma_bf16(acc[mi][nt], ahi, &BUF[nt * 4]);                  \
                    mma_bf16(acc[mi][nt], alo, &BUF[nt * 4]);                  \
                    mma_bf16(acc[mi][nt], ahi, &BUF[nt * 4 + 2]);              \
                }                                                              \
            }                                                                  \
        }                                                                      \
    }

    #pragma unroll 1
    for (int kt = 0; kt < 62; kt += 2) {
        C2_EPOCH(kt, bufA, bufB, kt + 1);
        C2_EPOCH(kt + 1, bufB, bufA, (kt + 2 < 63) ? (kt + 2) : 62);
    }
    C2_EPOCH(62, bufA, bufB, 62);
    #undef C2_EPOCH

    #pragma unroll
    for (int mi = 0; mi < 2; mi++) {
        const int m = wid + 4 * mi;
        if (m >= 7) continue;
        #pragma unroll
        for (int h = 0; h < 2; h++) {
            const int r = m * 16 + gr + 8 * h;
            if (r >= 100) continue;
            u32* op = &g_h2b[(size_t)img * 2000 + r];
            #pragma unroll
            for (int nt = 0; nt < 3; nt++) {
                const int oc0 = nt * 8 + 2 * t4;
                if (oc0 < 20) {
                    const float v0 = acc[mi][nt][2 * h] + __ldg(&b2[oc0]);
                    op[oc0 * 100] = splitpk(fmaxf(v0, 0.0f));
                }
                if (oc0 + 1 < 20) {
                    const float v1 = acc[mi][nt][2 * h + 1] + __ldg(&b2[oc0 + 1]);
                    op[(oc0 + 1) * 100] = splitpk(fmaxf(v1, 0.0f));
                }
            }
        }
    }
}

// ---------------------------------------------------------------------------
// conv3 via MMA + FC (R16) with ping-pong B buffers.
// ---------------------------------------------------------------------------
__global__ __launch_bounds__(128) void conv3_mma_fc_kernel(
    const float* __restrict__ b3, const float* __restrict__ bf,
    float* __restrict__ out)
{
    __shared__ u32 s_pl[8000];
    __shared__ u32 s_koff[38 * 8];
    __shared__ float s_hf[2][720];
    __shared__ float s_rlo[4][10], s_rhi[4][10];

    const int bid = blockIdx.x;
    const int tid = threadIdx.x;
    const int wid = tid >> 5, lane = tid & 31;
    const int t4 = lane & 3, gr = lane >> 2;

    for (int i = tid; i < 8000; i += 128) s_pl[i] = 0;
    for (int i = tid; i < 304; i += 128) {
        const int kt = i >> 3, t4i = (i >> 1) & 3, p = i & 1;
        const int k0 = kt * 16 + 2 * t4i + 8 * p;
        u32 v = 0;
        if (k0 < 600) {
            const int c = k0 / 30, rem = k0 % 30;
            const int ky = rem / 6, kx = rem % 6;
            v = (u32)(c * 50 + ky * 5 + (kx >> 1));
        }
        s_koff[i] = v;
    }
    __syncthreads();

    {
        const u32* h2p = &g_h2b[(size_t)(2 * bid) * 2000];
        for (int i = tid; i < 4000; i += 128) {
            const int img = i / 2000, rem = i % 2000;
            const int rowc = rem / 10, ix = rem % 10;
            const u32 v = h2p[i];
            const u16 hi = (u16)(v & 0xffffu);
            const u16 lo = (u16)(v >> 16);
            u16* base = (u16*)&s_pl[img * 4000];
            const int e0 = (rowc * 5 + (ix >> 1)) * 2 + (ix & 1);
            base[e0]        = hi;
            base[4000 + e0] = lo;
            if (ix > 0) {
                const int e1 = (rowc * 5 + ((ix - 1) >> 1)) * 2 + ((ix - 1) & 1);
                base[2000 + e1] = hi;
                base[6000 + e1] = lo;
            }
        }
    }

    float acc[2][3][4];
    #pragma unroll
    for (int mi = 0; mi < 2; mi++)
        #pragma unroll
        for (int nt = 0; nt < 3; nt++)
            #pragma unroll
            for (int r = 0; r < 4; r++) acc[mi][nt][r] = 0.0f;

    u32 abase[2][2];
    #pragma unroll
    for (int mi = 0; mi < 2; mi++) {
        const int m = wid + 4 * mi;
        #pragma unroll
        for (int h = 0; h < 2; h++) {
            const int r = m * 16 + gr + 8 * h;
            const int img = r / 48, pos = r % 48;
            const bool v = (m < 6) && (pos < 36);
            const int oy = pos / 6, ox = pos % 6;
            abase[mi][h] = v ? (u32)(img * 4000 + (ox & 1) * 1000 + oy * 5 + (ox >> 1)) : 0u;
        }
    }
    __syncthreads();

    u32 bufA[12], bufB[12];
    {
        const u32* bp = &g_w3frag[lane];
        #pragma unroll
        for (int j = 0; j < 12; j++) bufA[j] = __ldg(bp + j * 32);
    }

    #define C3_EPOCH(KT, BUF, NBUF, NKT)                                       \
    {                                                                          \
        {                                                                      \
            const u32* bp = &g_w3frag[(NKT) * 384 + lane];                     \
            _Pragma("unroll")                                                  \
            for (int j = 0; j < 12; j++) NBUF[j] = __ldg(bp + j * 32);         \
        }                                                                      \
        const u32 ko0 = s_koff[(KT) * 8 + t4 * 2];                             \
        const u32 ko1 = s_koff[(KT) * 8 + t4 * 2 + 1];                         \
        _Pragma("unroll")                                                      \
        for (int mi = 0; mi < 2; mi++) {                                       \
            if (wid + 4 * mi < 6) {                                            \
                u32 ahi[4], alo[4];                                            \
                _Pragma("unroll")                                              \
                for (int h = 0; h < 2; h++) {                                  \
                    const u32 i0 = abase[mi][h] + ko0;                         \
                    const u32 i1 = abase[mi][h] + ko1;                         \
                    ahi[h]     = s_pl[i0];  alo[h]     = s_pl[i0 + 2000];      \
                    ahi[h + 2] = s_pl[i1];  alo[h + 2] = s_pl[i1 + 2000];      \
                }                                                              \
                _Pragma("unroll")                                              \
                for (int nt = 0; nt < 3; nt++) {                               \
                    mma_bf16(acc[mi][nt], ahi, &BUF[nt * 4]);                  \
                    mma_bf16(acc[mi][nt], alo, &BUF[nt * 4]);                  \
                    mma_bf16(acc[mi][nt], ahi, &BUF[nt * 4 + 2]);              \
                }                                                              \
            }                                                                  \
        }                                                                      \
    }

    #pragma unroll 1
    for (int kt = 0; kt < 36; kt += 2) {
        C3_EPOCH(kt, bufA, bufB, kt + 1);
        C3_EPOCH(kt + 1, bufB, bufA, (kt + 2 < 38) ? (kt + 2) : 37);
    }
    C3_EPOCH(36, bufA, bufB, 37);
    C3_EPOCH(37, bufB, bufA, 37);
    #undef C3_EPOCH

    #pragma unroll
    for (int mi = 0; mi < 2; mi++) {
        const int m = wid + 4 * mi;
        if (m >= 6) continue;
        #pragma unroll
        for (int h = 0; h < 2; h++) {
            const int r = m * 16 + gr + 8 * h;
            const int img = r / 48, pos = r % 48;
            if (pos >= 36) continue;
            #pragma unroll
            for (int nt = 0; nt < 3; nt++) {
                const int oc0 = nt * 8 + 2 * t4;
                if (oc0 < 20) {
                    const float v0 = acc[mi][nt][2 * h] + __ldg(&b3[oc0]);
                    s_hf[img][oc0 * 36 + pos] = fmaxf(v0, 0.0f);
                }
                if (oc0 + 1 < 20) {
                    const float v1 = acc[mi][nt][2 * h + 1] + __ldg(&b3[oc0 + 1]);
                    s_hf[img][(oc0 + 1) * 36 + pos] = fmaxf(v1, 0.0f);
                }
            }
        }
    }
    __syncthreads();

    {
        u64 a[10];
        #pragma unroll
        for (int o = 0; o < 10; o++) a[o] = 0ULL;
        for (int j = tid; j < 720; j += 128) {
            const u64 v2 = pack2(s_hf[0][j], s_hf[1][j]);
            #pragma unroll
            for (int o = 0; o < 10; o++)
                a[o] = fma2(v2, __ldg(&g_wfp[o * 720 + j]), a[o]);
        }
        const int wd = tid >> 5;
        #pragma unroll
        for (int o = 0; o < 10; o++) {
            float lo, hi; unpack2(a[o], lo, hi);
            #pragma unroll
            for (int s = 16; s > 0; s >>= 1) {
                lo += __shfl_down_sync(0xffffffffu, lo, s);
                hi += __shfl_down_sync(0xffffffffu, hi, s);
            }
            if ((tid & 31) == 0) { s_rlo[wd][o] = lo; s_rhi[wd][o] = hi; }
        }
    }
    __syncthreads();
    if (tid < 20) {
        const int o = tid % 10;
        const int im = tid / 10;
        float v;
        if (im == 0) v = s_rlo[0][o] + s_rlo[1][o] + s_rlo[2][o] + s_rlo[3][o];
        else         v = s_rhi[0][o] + s_rhi[1][o] + s_rhi[2][o] + s_rhi[3][o];
        out[(size_t)(2 * bid + im) * 10 + o] = v + __ldg(&bf[o]);
    }
}

// ---------------------------------------------------------------------------
extern "C" void kernel_launch(void* const* d_in, const int* in_sizes, int n_in,
                              void* d_out, int out_size)
{
    (void)in_sizes; (void)n_in; (void)out_size;
    const float* x  = (const float*)d_in[0];
    const float* w1 = (const float*)d_in[1];
    const float* b1 = (const float*)d_in[2];
    const float* w2 = (const float*)d_in[3];
    const float* b2 = (const float*)d_in[4];
    const float* w3 = (const float*)d_in[5];
    const float* b3 = (const float*)d_in[6];
    const float* wf = (const float*)d_in[7];
    const float* bf = (const float*)d_in[8];
    float* out = (float*)d_out;

    pack_all_kernel<<<188, 256>>>(w1, w2, w3, wf);
    conv1_mma_kernel<<<BATCH, 128>>>(x, b1);
    conv2_mma_kernel<<<BATCH, 128>>>(b2);
    conv3_mma_fc_kernel<<<NPAIR, 128>>>(b3, bf, out);
}